// round 13
// baseline (speedup 1.0000x reference)
#include <cuda_runtime.h>
#include <math.h>

#define NB 256
#define ND 1024
#define NK 7
#define NVOC 32000

// ---------------- scratch (static device globals; no allocation) ----------------
__device__ float g_xcat[NB * 2 * ND];   // [h | f_emb] per row (2048 wide)
__device__ float g_c[NB * ND];          // h@U[k] + f@V[k]
__device__ float g_zA[NB * ND];
__device__ float g_zB[NB * ND];
__device__ float g_stabh[NB * ND];
__device__ float g_alocal[NB * ND];
__device__ float g_gamma[NB];
__device__ int   g_ksel[NB];
__device__ int   g_rows[NK * NB];
__device__ int   g_cnt[NK];

// ---------------- f32x2 helpers ----------------
__device__ __forceinline__ unsigned long long fma2(unsigned long long a,
                                                   unsigned long long b,
                                                   unsigned long long c) {
    unsigned long long d;
    asm("fma.rn.f32x2 %0, %1, %2, %3;" : "=l"(d) : "l"(a), "l"(b), "l"(c));
    return d;
}
__device__ __forceinline__ unsigned long long pack2(float x, float y) {
    unsigned int lo = __float_as_uint(x), hi = __float_as_uint(y);
    return ((unsigned long long)hi << 32) | (unsigned long long)lo;
}
__device__ __forceinline__ float2 unpack2(unsigned long long v) {
    return make_float2(__uint_as_float((unsigned int)(v & 0xffffffffull)),
                       __uint_as_float((unsigned int)(v >> 32)));
}
__device__ __forceinline__ float sigmoidf_(float x) { return 1.0f / (1.0f + expf(-x)); }

// ---------------- prep: embeddings, routing, gamma, pi ----------------
__global__ void prep_kernel(const float* __restrict__ h, const float* __restrict__ fiber_s,
                            const float* __restrict__ fiber_e, const int* __restrict__ token_idx,
                            const float* __restrict__ op_emb, const float* __restrict__ num_w,
                            const float* __restrict__ num_b, const float* __restrict__ addr,
                            const float* __restrict__ fs_w, const float* __restrict__ fs_b,
                            const float* __restrict__ fe_w, const float* __restrict__ fe_b,
                            const float* __restrict__ c1w, const float* __restrict__ c1b,
                            const float* __restrict__ c2w, const float* __restrict__ c2b,
                            float* __restrict__ pi_out) {
    int b = blockIdx.x;
    int tid = threadIdx.x;
    int tok = token_idx[b];
    bool isnum = tok >= 7;
    float numval = (float)tok - 7.0f;
    int opk = min(max(tok, 0), 6);
    float fsv = fiber_s[b], fev = fiber_e[b];

    float acc[23];  // 0:|te|^2 1:|te+f|^2 2..8:te.A_k 9..15:(te+f).A_k 16..22:|A_k|^2
#pragma unroll
    for (int i = 0; i < 23; i++) acc[i] = 0.f;

#pragma unroll
    for (int j = 0; j < 4; j++) {
        int d = tid + j * 256;
        float te = isnum ? (numval * num_w[d] + num_b[d]) : op_emb[opk * ND + d];
        float fv = tanhf(fsv * fs_w[d] + fs_b[d] + fev * fe_w[d] + fe_b[d]);
        g_xcat[(size_t)b * 2 * ND + d] = h[(size_t)b * ND + d];
        g_xcat[(size_t)b * 2 * ND + ND + d] = fv;
        float tf = te + fv;
        acc[0] += te * te;
        acc[1] += tf * tf;
#pragma unroll
        for (int k = 0; k < 7; k++) {
            float a = addr[k * ND + d];
            acc[2 + k] += te * a;
            acc[9 + k] += tf * a;
            acc[16 + k] += a * a;
        }
    }
    __shared__ float sred[23][8];
    int lane = tid & 31, wid = tid >> 5;
#pragma unroll
    for (int i = 0; i < 23; i++) {
        float v = acc[i];
#pragma unroll
        for (int o = 16; o > 0; o >>= 1) v += __shfl_down_sync(0xffffffffu, v, o);
        if (lane == 0) sred[i][wid] = v;
    }
    __syncthreads();
    if (tid == 0) {
        float r[23];
#pragma unroll
        for (int i = 0; i < 23; i++) {
            float s = 0.f;
#pragma unroll
            for (int w = 0; w < 8; w++) s += sred[i][w];
            r[i] = s;
        }
        float nt = fmaxf(sqrtf(r[0]), 1e-12f);
        float ntf = fmaxf(sqrtf(r[1]), 1e-12f);
        bool ctrl = tok < 7;
        float sc[7];
#pragma unroll
        for (int k = 0; k < 7; k++) {
            float na = fmaxf(sqrtf(r[16 + k]), 1e-12f);
            sc[k] = ctrl ? r[2 + k] / (nt * na) : r[9 + k] / (ntf * na);
        }
        float mx = -1e30f;
#pragma unroll
        for (int k = 0; k < 7; k++) mx = fmaxf(mx, 5.0f * sc[k]);
        float ex[7], se = 0.f;
#pragma unroll
        for (int k = 0; k < 7; k++) { ex[k] = expf(5.0f * sc[k] - mx); se += ex[k]; }
        int am = 0;
        float best = -1.0f, ent = 0.f;
#pragma unroll
        for (int k = 0; k < 7; k++) {
            float p = ex[k] / se;
            pi_out[b * 7 + k] = p;
            if (p > best) { best = p; am = k; }   // first-max, matches jnp.argmax
            ent -= p * logf(p + 1e-8f);
        }
        g_ksel[b] = am;
        float gsum = c2b[0];
#pragma unroll
        for (int j = 0; j < 16; j++) {
            float hv = c1w[j * 2 + 0] * ent + c1b[j];  // seq_position = 0
            hv = fmaxf(hv, 0.f);
            gsum += c2w[j] * hv;
        }
        // softplus = max(x,0) + log1p(exp(-|x|))
        g_gamma[b] = fmaxf(gsum, 0.f) + log1pf(expf(-fabsf(gsum)));
    }
}

// ---------------- group rows by selected gremlin (deterministic) ----------------
__global__ void group_kernel() {
    int k = threadIdx.x;
    if (k >= NK) return;
    int c = 0;
    for (int b = 0; b < NB; b++)
        if (g_ksel[b] == k) g_rows[k * NB + (c++)] = b;
    g_cnt[k] = c;
}

// ---------------- generic GEMM  C[M,N] = epi(A[M,K] @ B[N,K]^T + bias) ----------
// BM=64, BN=64, BK=32, 256 threads, 4x4 micro-tile with f32x2 on N.
// EPI: 0 = +bias, 1 = tanh(+bias), 2 = sigmoid(+bias)
template <int EPI>
__global__ void __launch_bounds__(256) gemm_nt(const float* __restrict__ A, int lda,
                                               const float* __restrict__ Bm, int ldb,
                                               const float* __restrict__ bias,
                                               float* __restrict__ C, int ldc, int Kdim) {
    __shared__ unsigned long long As2[32][64];  // duplicated-pair A
    __shared__ float Bs[32][64];
    const int m0 = blockIdx.x * 64, n0 = blockIdx.y * 64;
    const int tid = threadIdx.x;
    const int tn = tid & 15, tm = tid >> 4;
    unsigned long long accv[4][2];
#pragma unroll
    for (int r = 0; r < 4; r++) { accv[r][0] = 0ull; accv[r][1] = 0ull; }
    const int lm = tid >> 3;
    const int lk = (tid & 7) << 2;
    for (int k0 = 0; k0 < Kdim; k0 += 32) {
#pragma unroll
        for (int q = 0; q < 2; q++) {
            int m = lm + q * 32;
            float4 v = *(const float4*)(A + (size_t)(m0 + m) * lda + (k0 + lk));
            As2[lk + 0][m] = pack2(v.x, v.x);
            As2[lk + 1][m] = pack2(v.y, v.y);
            As2[lk + 2][m] = pack2(v.z, v.z);
            As2[lk + 3][m] = pack2(v.w, v.w);
            float4 w = *(const float4*)(Bm + (size_t)(n0 + m) * ldb + (k0 + lk));
            Bs[lk + 0][m] = w.x; Bs[lk + 1][m] = w.y; Bs[lk + 2][m] = w.z; Bs[lk + 3][m] = w.w;
        }
        __syncthreads();
#pragma unroll
        for (int kk = 0; kk < 32; kk++) {
            ulonglong2 b = *(const ulonglong2*)&Bs[kk][tn * 4];
            ulonglong2 a01 = *(const ulonglong2*)&As2[kk][tm * 4];
            ulonglong2 a23 = *(const ulonglong2*)&As2[kk][tm * 4 + 2];
            accv[0][0] = fma2(a01.x, b.x, accv[0][0]); accv[0][1] = fma2(a01.x, b.y, accv[0][1]);
            accv[1][0] = fma2(a01.y, b.x, accv[1][0]); accv[1][1] = fma2(a01.y, b.y, accv[1][1]);
            accv[2][0] = fma2(a23.x, b.x, accv[2][0]); accv[2][1] = fma2(a23.x, b.y, accv[2][1]);
            accv[3][0] = fma2(a23.y, b.x, accv[3][0]); accv[3][1] = fma2(a23.y, b.y, accv[3][1]);
        }
        __syncthreads();
    }
    int n = n0 + tn * 4;
    float4 bv = *(const float4*)(bias + n);
#pragma unroll
    for (int r = 0; r < 4; r++) {
        int m = m0 + tm * 4 + r;
        float2 p0 = unpack2(accv[r][0]);
        float2 p1 = unpack2(accv[r][1]);
        float4 o;
        o.x = p0.x + bv.x; o.y = p0.y + bv.y; o.z = p1.x + bv.z; o.w = p1.y + bv.w;
        if (EPI == 1) { o.x = tanhf(o.x); o.y = tanhf(o.y); o.z = tanhf(o.z); o.w = tanhf(o.w); }
        if (EPI == 2) { o.x = sigmoidf_(o.x); o.y = sigmoidf_(o.y); o.z = sigmoidf_(o.z); o.w = sigmoidf_(o.w); }
        *(float4*)(C + (size_t)m * ldc + n) = o;
    }
}

// ---------------- grouped GEMM over gremlin groups ----------------
// MODE 0: c[b,:] = h@U[k] + f@V[k] (K=2048 virtual), writes g_c and Zout=tanh(c)
// MODE 1: Zout[b,:] = tanh(Zin@W[k] + c[b,:])
// BM=32, BN=64, BK=32, 128 threads, 4x4 micro-tile.
template <int MODE>
__global__ void __launch_bounds__(128) gemm_group(const float* __restrict__ G1,
                                                  const float* __restrict__ G2,
                                                  const float* __restrict__ Zin,
                                                  float* __restrict__ Zout) {
    __shared__ unsigned long long As2[32][32];
    __shared__ float Bs[32][64];
    __shared__ int rs[32];
    const int kg = blockIdx.z;
    const int cnt = g_cnt[kg];
    const int mtile = blockIdx.x;
    if (mtile * 32 >= cnt) return;
    const int n0 = blockIdx.y * 64;
    const int tid = threadIdx.x;
    if (tid < 32) {
        int mi = mtile * 32 + tid;
        rs[tid] = g_rows[kg * NB + (mi < NB ? mi : (NB - 1))];
    }
    __syncthreads();
    const int tn = tid & 15, tm = tid >> 4;  // tm 0..7 -> 4 rows each
    unsigned long long accv[4][2];
#pragma unroll
    for (int r = 0; r < 4; r++) { accv[r][0] = 0ull; accv[r][1] = 0ull; }
    const int KD = (MODE == 0) ? 2048 : 1024;
    for (int k0 = 0; k0 < KD; k0 += 32) {
#pragma unroll
        for (int q = 0; q < 2; q++) {
            int id = tid + q * 128;
            int m = id >> 3, kq = (id & 7) << 2;
            int rr = rs[m];
            const float* ap = (MODE == 0) ? (g_xcat + (size_t)rr * 2048 + k0 + kq)
                                          : (Zin + (size_t)rr * ND + k0 + kq);
            float4 v = *(const float4*)ap;
            As2[kq + 0][m] = pack2(v.x, v.x);
            As2[kq + 1][m] = pack2(v.y, v.y);
            As2[kq + 2][m] = pack2(v.z, v.z);
            As2[kq + 3][m] = pack2(v.w, v.w);
        }
#pragma unroll
        for (int q = 0; q < 4; q++) {
            int id = tid + q * 128;
            int kk = id >> 4, eq = (id & 15) << 2;
            int kglob = k0 + kk;
            const float* bp;
            if (MODE == 0) {
                bp = (kglob < 1024)
                         ? (G1 + (size_t)kg * ND * ND + (size_t)kglob * ND + n0 + eq)
                         : (G2 + (size_t)kg * ND * ND + (size_t)(kglob - 1024) * ND + n0 + eq);
            } else {
                bp = G1 + (size_t)kg * ND * ND + (size_t)kglob * ND + n0 + eq;
            }
            *(float4*)&Bs[kk][eq] = *(const float4*)bp;
        }
        __syncthreads();
#pragma unroll
        for (int kk = 0; kk < 32; kk++) {
            ulonglong2 b = *(const ulonglong2*)&Bs[kk][tn * 4];
            ulonglong2 a01 = *(const ulonglong2*)&As2[kk][tm * 4];
            ulonglong2 a23 = *(const ulonglong2*)&As2[kk][tm * 4 + 2];
            accv[0][0] = fma2(a01.x, b.x, accv[0][0]); accv[0][1] = fma2(a01.x, b.y, accv[0][1]);
            accv[1][0] = fma2(a01.y, b.x, accv[1][0]); accv[1][1] = fma2(a01.y, b.y, accv[1][1]);
            accv[2][0] = fma2(a23.x, b.x, accv[2][0]); accv[2][1] = fma2(a23.x, b.y, accv[2][1]);
            accv[3][0] = fma2(a23.y, b.x, accv[3][0]); accv[3][1] = fma2(a23.y, b.y, accv[3][1]);
        }
        __syncthreads();
    }
    int n = n0 + tn * 4;
#pragma unroll
    for (int r = 0; r < 4; r++) {
        int mi = mtile * 32 + tm * 4 + r;
        if (mi < cnt) {
            int row = rs[tm * 4 + r];
            float2 p0 = unpack2(accv[r][0]);
            float2 p1 = unpack2(accv[r][1]);
            if (MODE == 0) {
                float4 cv = make_float4(p0.x, p0.y, p1.x, p1.y);
                *(float4*)(g_c + (size_t)row * ND + n) = cv;
                float4 zv = make_float4(tanhf(cv.x), tanhf(cv.y), tanhf(cv.z), tanhf(cv.w));
                *(float4*)(Zout + (size_t)row * ND + n) = zv;
            } else {
                float4 cv = *(const float4*)(g_c + (size_t)row * ND + n);
                float4 zv = make_float4(tanhf(p0.x + cv.x), tanhf(p0.y + cv.y),
                                        tanhf(p1.x + cv.z), tanhf(p1.y + cv.w));
                *(float4*)(Zout + (size_t)row * ND + n) = zv;
            }
        }
    }
}

// ---------------- h_next = h + gamma * alpha_local * z_star ----------------
__global__ void combine_kernel(const float* __restrict__ h, const float* __restrict__ z,
                               float* __restrict__ out) {
    int i = blockIdx.x * 256 + threadIdx.x;
    int b = i >> 10;
    out[i] = fmaf(g_gamma[b] * g_alocal[i], z[i], h[i]);
}

// ---------------- launch ----------------
extern "C" void kernel_launch(void* const* d_in, const int* in_sizes, int n_in,
                              void* d_out, int out_size) {
    (void)in_sizes; (void)n_in; (void)out_size;
    const float* h        = (const float*)d_in[0];
    const float* fiber_s  = (const float*)d_in[1];
    const float* fiber_e  = (const float*)d_in[2];
    const int*   token_idx= (const int*)d_in[3];
    const float* op_emb   = (const float*)d_in[4];
    const float* num_w    = (const float*)d_in[5];
    const float* num_b    = (const float*)d_in[6];
    const float* addr     = (const float*)d_in[7];
    const float* W        = (const float*)d_in[8];
    const float* U        = (const float*)d_in[9];
    const float* V        = (const float*)d_in[10];
    const float* fs_w     = (const float*)d_in[11];
    const float* fs_b     = (const float*)d_in[12];
    const float* fe_w     = (const float*)d_in[13];
    const float* fe_b     = (const float*)d_in[14];
    const float* s1w      = (const float*)d_in[15];
    const float* s1b      = (const float*)d_in[16];
    const float* s2w      = (const float*)d_in[17];
    const float* s2b      = (const float*)d_in[18];
    const float* c1w      = (const float*)d_in[19];
    const float* c1b      = (const float*)d_in[20];
    const float* c2w      = (const float*)d_in[21];
    const float* c2b      = (const float*)d_in[22];
    const float* dec_w    = (const float*)d_in[23];
    const float* dec_b    = (const float*)d_in[24];

    float *xcat, *stabh, *alocal, *zA, *zB;
    cudaGetSymbolAddress((void**)&xcat, g_xcat);
    cudaGetSymbolAddress((void**)&stabh, g_stabh);
    cudaGetSymbolAddress((void**)&alocal, g_alocal);
    cudaGetSymbolAddress((void**)&zA, g_zA);
    cudaGetSymbolAddress((void**)&zB, g_zB);

    float* out        = (float*)d_out;
    float* out_h      = out;                          // [256,1024]
    float* out_logits = out + (size_t)NB * ND;        // [256,32000]
    float* out_pi     = out + (size_t)NB * ND + (size_t)NB * NVOC;  // [256,7]

    prep_kernel<<<NB, 256>>>(h, fiber_s, fiber_e, token_idx, op_emb, num_w, num_b, addr,
                             fs_w, fs_b, fe_w, fe_b, c1w, c1b, c2w, c2b, out_pi);
    group_kernel<<<1, 32>>>();

    // stab network (independent of DEQ)
    gemm_nt<1><<<dim3(4, 16), 256>>>(xcat, 2048, s1w, 2048, s1b, stabh, 1024, 2048);
    gemm_nt<2><<<dim3(4, 16), 256>>>(stabh, 1024, s2w, 1024, s2b, alocal, 1024, 1024);

    // c = h@U[k] + f@V[k]; z1 = tanh(c)   (body step 1 of the DEQ)
    gemm_group<0><<<dim3(8, 16, 7), 128>>>(U, V, nullptr, zA);

    // 39 more body steps -> z40 (reference does <= 40; extra steps converge identically)
    const float* zin = zA;
    float* zout = zB;
    for (int it = 0; it < 39; it++) {
        gemm_group<1><<<dim3(8, 16, 7), 128>>>(W, nullptr, zin, zout);
        float* t = zout; zout = (float*)zin; zin = t;
    }

    combine_kernel<<<1024, 256>>>(h, zin, out_h);

    // decoder: logits = h_next @ dec_w^T + dec_b
    gemm_nt<0><<<dim3(4, 500), 256>>>(out_h, 1024, dec_w, 1024, dec_b, out_logits, 32000, 1024);
}

// round 14
// speedup vs baseline: 1.0060x; 1.0060x over previous
#include <cuda_runtime.h>
#include <math.h>

#define NB 256
#define ND 1024
#define NK 7
#define NVOC 32000

// ---------------- scratch (static device globals; no allocation) ----------------
__device__ float g_xcat[NB * 2 * ND];   // [h | f_emb] per row (2048 wide)
__device__ float g_c[NB * ND];          // h@U[k] + f@V[k]
__device__ float g_zA[NB * ND];
__device__ float g_zB[NB * ND];
__device__ float g_stabh[NB * ND];
__device__ float g_alocal[NB * ND];
__device__ float g_gamma[NB];
__device__ int   g_ksel[NB];
__device__ int   g_rows[NK * NB];
__device__ int   g_cnt[NK];

// ---------------- f32x2 helpers ----------------
__device__ __forceinline__ unsigned long long fma2(unsigned long long a,
                                                   unsigned long long b,
                                                   unsigned long long c) {
    unsigned long long d;
    asm("fma.rn.f32x2 %0, %1, %2, %3;" : "=l"(d) : "l"(a), "l"(b), "l"(c));
    return d;
}
__device__ __forceinline__ unsigned long long pack2(float x, float y) {
    unsigned int lo = __float_as_uint(x), hi = __float_as_uint(y);
    return ((unsigned long long)hi << 32) | (unsigned long long)lo;
}
__device__ __forceinline__ float2 unpack2(unsigned long long v) {
    return make_float2(__uint_as_float((unsigned int)(v & 0xffffffffull)),
                       __uint_as_float((unsigned int)(v >> 32)));
}
__device__ __forceinline__ float sigmoidf_(float x) { return 1.0f / (1.0f + expf(-x)); }

// ---------------- prep: embeddings, routing, gamma, pi ----------------
__global__ void prep_kernel(const float* __restrict__ h, const float* __restrict__ fiber_s,
                            const float* __restrict__ fiber_e, const int* __restrict__ token_idx,
                            const float* __restrict__ op_emb, const float* __restrict__ num_w,
                            const float* __restrict__ num_b, const float* __restrict__ addr,
                            const float* __restrict__ fs_w, const float* __restrict__ fs_b,
                            const float* __restrict__ fe_w, const float* __restrict__ fe_b,
                            const float* __restrict__ c1w, const float* __restrict__ c1b,
                            const float* __restrict__ c2w, const float* __restrict__ c2b,
                            float* __restrict__ pi_out) {
    int b = blockIdx.x;
    int tid = threadIdx.x;
    int tok = token_idx[b];
    bool isnum = tok >= 7;
    float numval = (float)tok - 7.0f;
    int opk = min(max(tok, 0), 6);
    float fsv = fiber_s[b], fev = fiber_e[b];

    float acc[23];  // 0:|te|^2 1:|te+f|^2 2..8:te.A_k 9..15:(te+f).A_k 16..22:|A_k|^2
#pragma unroll
    for (int i = 0; i < 23; i++) acc[i] = 0.f;

#pragma unroll
    for (int j = 0; j < 4; j++) {
        int d = tid + j * 256;
        float te = isnum ? (numval * num_w[d] + num_b[d]) : op_emb[opk * ND + d];
        float fv = tanhf(fsv * fs_w[d] + fs_b[d] + fev * fe_w[d] + fe_b[d]);
        g_xcat[(size_t)b * 2 * ND + d] = h[(size_t)b * ND + d];
        g_xcat[(size_t)b * 2 * ND + ND + d] = fv;
        float tf = te + fv;
        acc[0] += te * te;
        acc[1] += tf * tf;
#pragma unroll
        for (int k = 0; k < 7; k++) {
            float a = addr[k * ND + d];
            acc[2 + k] += te * a;
            acc[9 + k] += tf * a;
            acc[16 + k] += a * a;
        }
    }
    __shared__ float sred[23][8];
    int lane = tid & 31, wid = tid >> 5;
#pragma unroll
    for (int i = 0; i < 23; i++) {
        float v = acc[i];
#pragma unroll
        for (int o = 16; o > 0; o >>= 1) v += __shfl_down_sync(0xffffffffu, v, o);
        if (lane == 0) sred[i][wid] = v;
    }
    __syncthreads();
    if (tid == 0) {
        float r[23];
#pragma unroll
        for (int i = 0; i < 23; i++) {
            float s = 0.f;
#pragma unroll
            for (int w = 0; w < 8; w++) s += sred[i][w];
            r[i] = s;
        }
        float nt = fmaxf(sqrtf(r[0]), 1e-12f);
        float ntf = fmaxf(sqrtf(r[1]), 1e-12f);
        bool ctrl = tok < 7;
        float sc[7];
#pragma unroll
        for (int k = 0; k < 7; k++) {
            float na = fmaxf(sqrtf(r[16 + k]), 1e-12f);
            sc[k] = ctrl ? r[2 + k] / (nt * na) : r[9 + k] / (ntf * na);
        }
        float mx = -1e30f;
#pragma unroll
        for (int k = 0; k < 7; k++) mx = fmaxf(mx, 5.0f * sc[k]);
        float ex[7], se = 0.f;
#pragma unroll
        for (int k = 0; k < 7; k++) { ex[k] = expf(5.0f * sc[k] - mx); se += ex[k]; }
        int am = 0;
        float best = -1.0f, ent = 0.f;
#pragma unroll
        for (int k = 0; k < 7; k++) {
            float p = ex[k] / se;
            pi_out[b * 7 + k] = p;
            if (p > best) { best = p; am = k; }   // first-max, matches jnp.argmax
            ent -= p * logf(p + 1e-8f);
        }
        g_ksel[b] = am;
        float gsum = c2b[0];
#pragma unroll
        for (int j = 0; j < 16; j++) {
            float hv = c1w[j * 2 + 0] * ent + c1b[j];  // seq_position = 0
            hv = fmaxf(hv, 0.f);
            gsum += c2w[j] * hv;
        }
        // softplus = max(x,0) + log1p(exp(-|x|))
        g_gamma[b] = fmaxf(gsum, 0.f) + log1pf(expf(-fabsf(gsum)));
    }
}

// ---------------- group rows by selected gremlin (deterministic) ----------------
__global__ void group_kernel() {
    int k = threadIdx.x;
    if (k >= NK) return;
    int c = 0;
    for (int b = 0; b < NB; b++)
        if (g_ksel[b] == k) g_rows[k * NB + (c++)] = b;
    g_cnt[k] = c;
}

// ---------------- generic GEMM  C[M,N] = epi(A[M,K] @ B[N,K]^T + bias) ----------
// BM=64, BN=64, BK=32, 256 threads, 4x4 micro-tile with f32x2 on N.
// EPI: 0 = +bias, 1 = tanh(+bias), 2 = sigmoid(+bias)
template <int EPI>
__global__ void __launch_bounds__(256) gemm_nt(const float* __restrict__ A, int lda,
                                               const float* __restrict__ Bm, int ldb,
                                               const float* __restrict__ bias,
                                               float* __restrict__ C, int ldc, int Kdim) {
    __shared__ unsigned long long As2[32][64];  // duplicated-pair A
    __shared__ float Bs[32][64];
    const int m0 = blockIdx.x * 64, n0 = blockIdx.y * 64;
    const int tid = threadIdx.x;
    const int tn = tid & 15, tm = tid >> 4;
    unsigned long long accv[4][2];
#pragma unroll
    for (int r = 0; r < 4; r++) { accv[r][0] = 0ull; accv[r][1] = 0ull; }
    const int lm = tid >> 3;
    const int lk = (tid & 7) << 2;
    for (int k0 = 0; k0 < Kdim; k0 += 32) {
#pragma unroll
        for (int q = 0; q < 2; q++) {
            int m = lm + q * 32;
            float4 v = *(const float4*)(A + (size_t)(m0 + m) * lda + (k0 + lk));
            As2[lk + 0][m] = pack2(v.x, v.x);
            As2[lk + 1][m] = pack2(v.y, v.y);
            As2[lk + 2][m] = pack2(v.z, v.z);
            As2[lk + 3][m] = pack2(v.w, v.w);
            float4 w = *(const float4*)(Bm + (size_t)(n0 + m) * ldb + (k0 + lk));
            Bs[lk + 0][m] = w.x; Bs[lk + 1][m] = w.y; Bs[lk + 2][m] = w.z; Bs[lk + 3][m] = w.w;
        }
        __syncthreads();
#pragma unroll
        for (int kk = 0; kk < 32; kk++) {
            ulonglong2 b = *(const ulonglong2*)&Bs[kk][tn * 4];
            ulonglong2 a01 = *(const ulonglong2*)&As2[kk][tm * 4];
            ulonglong2 a23 = *(const ulonglong2*)&As2[kk][tm * 4 + 2];
            accv[0][0] = fma2(a01.x, b.x, accv[0][0]); accv[0][1] = fma2(a01.x, b.y, accv[0][1]);
            accv[1][0] = fma2(a01.y, b.x, accv[1][0]); accv[1][1] = fma2(a01.y, b.y, accv[1][1]);
            accv[2][0] = fma2(a23.x, b.x, accv[2][0]); accv[2][1] = fma2(a23.x, b.y, accv[2][1]);
            accv[3][0] = fma2(a23.y, b.x, accv[3][0]); accv[3][1] = fma2(a23.y, b.y, accv[3][1]);
        }
        __syncthreads();
    }
    int n = n0 + tn * 4;
    float4 bv = *(const float4*)(bias + n);
#pragma unroll
    for (int r = 0; r < 4; r++) {
        int m = m0 + tm * 4 + r;
        float2 p0 = unpack2(accv[r][0]);
        float2 p1 = unpack2(accv[r][1]);
        float4 o;
        o.x = p0.x + bv.x; o.y = p0.y + bv.y; o.z = p1.x + bv.z; o.w = p1.y + bv.w;
        if (EPI == 1) { o.x = tanhf(o.x); o.y = tanhf(o.y); o.z = tanhf(o.z); o.w = tanhf(o.w); }
        if (EPI == 2) { o.x = sigmoidf_(o.x); o.y = sigmoidf_(o.y); o.z = sigmoidf_(o.z); o.w = sigmoidf_(o.w); }
        *(float4*)(C + (size_t)m * ldc + n) = o;
    }
}

// ---------------- grouped GEMM over gremlin groups ----------------
// MODE 0: c[b,:] = h@U[k] + f@V[k] (K=2048 virtual), writes g_c and Zout=tanh(c)
// MODE 1: Zout[b,:] = tanh(Zin@W[k] + c[b,:])
// BM=32, BN=64, BK=32, 128 threads, 4x4 micro-tile.
template <int MODE>
__global__ void __launch_bounds__(128) gemm_group(const float* __restrict__ G1,
                                                  const float* __restrict__ G2,
                                                  const float* __restrict__ Zin,
                                                  float* __restrict__ Zout) {
    __shared__ unsigned long long As2[32][32];
    __shared__ float Bs[32][64];
    __shared__ int rs[32];
    const int kg = blockIdx.z;
    const int cnt = g_cnt[kg];
    const int mtile = blockIdx.x;
    if (mtile * 32 >= cnt) return;
    const int n0 = blockIdx.y * 64;
    const int tid = threadIdx.x;
    if (tid < 32) {
        int mi = mtile * 32 + tid;
        rs[tid] = g_rows[kg * NB + (mi < NB ? mi : (NB - 1))];
    }
    __syncthreads();
    const int tn = tid & 15, tm = tid >> 4;  // tm 0..7 -> 4 rows each
    unsigned long long accv[4][2];
#pragma unroll
    for (int r = 0; r < 4; r++) { accv[r][0] = 0ull; accv[r][1] = 0ull; }
    const int KD = (MODE == 0) ? 2048 : 1024;
    for (int k0 = 0; k0 < KD; k0 += 32) {
#pragma unroll
        for (int q = 0; q < 2; q++) {
            int id = tid + q * 128;
            int m = id >> 3, kq = (id & 7) << 2;
            int rr = rs[m];
            const float* ap = (MODE == 0) ? (g_xcat + (size_t)rr * 2048 + k0 + kq)
                                          : (Zin + (size_t)rr * ND + k0 + kq);
            float4 v = *(const float4*)ap;
            As2[kq + 0][m] = pack2(v.x, v.x);
            As2[kq + 1][m] = pack2(v.y, v.y);
            As2[kq + 2][m] = pack2(v.z, v.z);
            As2[kq + 3][m] = pack2(v.w, v.w);
        }
#pragma unroll
        for (int q = 0; q < 4; q++) {
            int id = tid + q * 128;
            int kk = id >> 4, eq = (id & 15) << 2;
            int kglob = k0 + kk;
            const float* bp;
            if (MODE == 0) {
                bp = (kglob < 1024)
                         ? (G1 + (size_t)kg * ND * ND + (size_t)kglob * ND + n0 + eq)
                         : (G2 + (size_t)kg * ND * ND + (size_t)(kglob - 1024) * ND + n0 + eq);
            } else {
                bp = G1 + (size_t)kg * ND * ND + (size_t)kglob * ND + n0 + eq;
            }
            *(float4*)&Bs[kk][eq] = *(const float4*)bp;
        }
        __syncthreads();
#pragma unroll
        for (int kk = 0; kk < 32; kk++) {
            ulonglong2 b = *(const ulonglong2*)&Bs[kk][tn * 4];
            ulonglong2 a01 = *(const ulonglong2*)&As2[kk][tm * 4];
            ulonglong2 a23 = *(const ulonglong2*)&As2[kk][tm * 4 + 2];
            accv[0][0] = fma2(a01.x, b.x, accv[0][0]); accv[0][1] = fma2(a01.x, b.y, accv[0][1]);
            accv[1][0] = fma2(a01.y, b.x, accv[1][0]); accv[1][1] = fma2(a01.y, b.y, accv[1][1]);
            accv[2][0] = fma2(a23.x, b.x, accv[2][0]); accv[2][1] = fma2(a23.x, b.y, accv[2][1]);
            accv[3][0] = fma2(a23.y, b.x, accv[3][0]); accv[3][1] = fma2(a23.y, b.y, accv[3][1]);
        }
        __syncthreads();
    }
    int n = n0 + tn * 4;
#pragma unroll
    for (int r = 0; r < 4; r++) {
        int mi = mtile * 32 + tm * 4 + r;
        if (mi < cnt) {
            int row = rs[tm * 4 + r];
            float2 p0 = unpack2(accv[r][0]);
            float2 p1 = unpack2(accv[r][1]);
            if (MODE == 0) {
                float4 cv = make_float4(p0.x, p0.y, p1.x, p1.y);
                *(float4*)(g_c + (size_t)row * ND + n) = cv;
                float4 zv = make_float4(tanhf(cv.x), tanhf(cv.y), tanhf(cv.z), tanhf(cv.w));
                *(float4*)(Zout + (size_t)row * ND + n) = zv;
            } else {
                float4 cv = *(const float4*)(g_c + (size_t)row * ND + n);
                float4 zv = make_float4(tanhf(p0.x + cv.x), tanhf(p0.y + cv.y),
                                        tanhf(p1.x + cv.z), tanhf(p1.y + cv.w));
                *(float4*)(Zout + (size_t)row * ND + n) = zv;
            }
        }
    }
}

// ---------------- h_next = h + gamma * alpha_local * z_star ----------------
__global__ void combine_kernel(const float* __restrict__ h, const float* __restrict__ z,
                               float* __restrict__ out) {
    int i = blockIdx.x * 256 + threadIdx.x;
    int b = i >> 10;
    out[i] = fmaf(g_gamma[b] * g_alocal[i], z[i], h[i]);
}

// ---------------- launch ----------------
extern "C" void kernel_launch(void* const* d_in, const int* in_sizes, int n_in,
                              void* d_out, int out_size) {
    (void)in_sizes; (void)n_in; (void)out_size;
    const float* h        = (const float*)d_in[0];
    const float* fiber_s  = (const float*)d_in[1];
    const float* fiber_e  = (const float*)d_in[2];
    const int*   token_idx= (const int*)d_in[3];
    const float* op_emb   = (const float*)d_in[4];
    const float* num_w    = (const float*)d_in[5];
    const float* num_b    = (const float*)d_in[6];
    const float* addr     = (const float*)d_in[7];
    const float* W        = (const float*)d_in[8];
    const float* U        = (const float*)d_in[9];
    const float* V        = (const float*)d_in[10];
    const float* fs_w     = (const float*)d_in[11];
    const float* fs_b     = (const float*)d_in[12];
    const float* fe_w     = (const float*)d_in[13];
    const float* fe_b     = (const float*)d_in[14];
    const float* s1w      = (const float*)d_in[15];
    const float* s1b      = (const float*)d_in[16];
    const float* s2w      = (const float*)d_in[17];
    const float* s2b      = (const float*)d_in[18];
    const float* c1w      = (const float*)d_in[19];
    const float* c1b      = (const float*)d_in[20];
    const float* c2w      = (const float*)d_in[21];
    const float* c2b      = (const float*)d_in[22];
    const float* dec_w    = (const float*)d_in[23];
    const float* dec_b    = (const float*)d_in[24];

    float *xcat, *stabh, *alocal, *zA, *zB;
    cudaGetSymbolAddress((void**)&xcat, g_xcat);
    cudaGetSymbolAddress((void**)&stabh, g_stabh);
    cudaGetSymbolAddress((void**)&alocal, g_alocal);
    cudaGetSymbolAddress((void**)&zA, g_zA);
    cudaGetSymbolAddress((void**)&zB, g_zB);

    float* out        = (float*)d_out;
    float* out_h      = out;                          // [256,1024]
    float* out_logits = out + (size_t)NB * ND;        // [256,32000]
    float* out_pi     = out + (size_t)NB * ND + (size_t)NB * NVOC;  // [256,7]

    prep_kernel<<<NB, 256>>>(h, fiber_s, fiber_e, token_idx, op_emb, num_w, num_b, addr,
                             fs_w, fs_b, fe_w, fe_b, c1w, c1b, c2w, c2b, out_pi);
    group_kernel<<<1, 32>>>();

    // stab network (independent of DEQ)
    gemm_nt<1><<<dim3(4, 16), 256>>>(xcat, 2048, s1w, 2048, s1b, stabh, 1024, 2048);
    gemm_nt<2><<<dim3(4, 16), 256>>>(stabh, 1024, s2w, 1024, s2b, alocal, 1024, 1024);

    // c = h@U[k] + f@V[k]; z1 = tanh(c)   (body step 1 of the DEQ)
    gemm_group<0><<<dim3(8, 16, 7), 128>>>(U, V, nullptr, zA);

    // 39 more body steps -> z40 (reference does <= 40; extra steps converge identically)
    const float* zin = zA;
    float* zout = zB;
    for (int it = 0; it < 39; it++) {
        gemm_group<1><<<dim3(8, 16, 7), 128>>>(W, nullptr, zin, zout);
        float* t = zout; zout = (float*)zin; zin = t;
    }

    combine_kernel<<<1024, 256>>>(h, zin, out_h);

    // decoder: logits = h_next @ dec_w^T + dec_b
    gemm_nt<0><<<dim3(4, 500), 256>>>(out_h, 1024, dec_w, 1024, dec_b, out_logits, 32000, 1024);
}

// round 15
// speedup vs baseline: 2.1130x; 2.1004x over previous
#include <cuda_runtime.h>
#include <math.h>

#define NB 256
#define ND 1024
#define NK 7
#define NVOC 32000
#define MAXT 14                 // max sum_k ceil(cnt_k/32)  (proved: <= 14)
#define GRID_DEQ (MAXT * 16)    // 224 blocks, one 32x64 tile each

// ---------------- scratch (static device globals; no allocation) ----------------
__device__ float g_xcat[NB * 2 * ND];   // [h | f_emb] per row (2048 wide)
__device__ float g_c[NB * ND];          // h@U[k] + f@V[k]
__device__ float g_zA[NB * ND];
__device__ float g_zB[NB * ND];
__device__ float g_stabh[NB * ND];
__device__ float g_alocal[NB * ND];
__device__ float g_gamma[NB];
__device__ int   g_ksel[NB];
__device__ int   g_rows[NK * NB];
__device__ int   g_cnt[NK];
__device__ int   g_mt_k[MAXT];
__device__ int   g_mt_m0[MAXT];
__device__ int   g_mtcnt;
__device__ float g_norms[GRID_DEQ];
__device__ unsigned g_cnt_bar;
__device__ unsigned g_epoch_v;
__device__ int   g_done_v;

// ---------------- f32x2 helpers ----------------
__device__ __forceinline__ unsigned long long fma2(unsigned long long a,
                                                   unsigned long long b,
                                                   unsigned long long c) {
    unsigned long long d;
    asm("fma.rn.f32x2 %0, %1, %2, %3;" : "=l"(d) : "l"(a), "l"(b), "l"(c));
    return d;
}
__device__ __forceinline__ unsigned long long pack2(float x, float y) {
    unsigned int lo = __float_as_uint(x), hi = __float_as_uint(y);
    return ((unsigned long long)hi << 32) | (unsigned long long)lo;
}
__device__ __forceinline__ float2 unpack2(unsigned long long v) {
    return make_float2(__uint_as_float((unsigned int)(v & 0xffffffffull)),
                       __uint_as_float((unsigned int)(v >> 32)));
}
__device__ __forceinline__ float sigmoidf_(float x) { return 1.0f / (1.0f + expf(-x)); }

// ---------------- prep: embeddings, routing, gamma, pi ----------------
__global__ void prep_kernel(const float* __restrict__ h, const float* __restrict__ fiber_s,
                            const float* __restrict__ fiber_e, const int* __restrict__ token_idx,
                            const float* __restrict__ op_emb, const float* __restrict__ num_w,
                            const float* __restrict__ num_b, const float* __restrict__ addr,
                            const float* __restrict__ fs_w, const float* __restrict__ fs_b,
                            const float* __restrict__ fe_w, const float* __restrict__ fe_b,
                            const float* __restrict__ c1w, const float* __restrict__ c1b,
                            const float* __restrict__ c2w, const float* __restrict__ c2b,
                            float* __restrict__ pi_out) {
    int b = blockIdx.x;
    int tid = threadIdx.x;
    int tok = token_idx[b];
    bool isnum = tok >= 7;
    float numval = (float)tok - 7.0f;
    int opk = min(max(tok, 0), 6);
    float fsv = fiber_s[b], fev = fiber_e[b];

    float acc[23];
#pragma unroll
    for (int i = 0; i < 23; i++) acc[i] = 0.f;

#pragma unroll
    for (int j = 0; j < 4; j++) {
        int d = tid + j * 256;
        float te = isnum ? (numval * num_w[d] + num_b[d]) : op_emb[opk * ND + d];
        float fv = tanhf(fsv * fs_w[d] + fs_b[d] + fev * fe_w[d] + fe_b[d]);
        g_xcat[(size_t)b * 2 * ND + d] = h[(size_t)b * ND + d];
        g_xcat[(size_t)b * 2 * ND + ND + d] = fv;
        float tf = te + fv;
        acc[0] += te * te;
        acc[1] += tf * tf;
#pragma unroll
        for (int k = 0; k < 7; k++) {
            float a = addr[k * ND + d];
            acc[2 + k] += te * a;
            acc[9 + k] += tf * a;
            acc[16 + k] += a * a;
        }
    }
    __shared__ float sred[23][8];
    int lane = tid & 31, wid = tid >> 5;
#pragma unroll
    for (int i = 0; i < 23; i++) {
        float v = acc[i];
#pragma unroll
        for (int o = 16; o > 0; o >>= 1) v += __shfl_down_sync(0xffffffffu, v, o);
        if (lane == 0) sred[i][wid] = v;
    }
    __syncthreads();
    if (tid == 0) {
        float r[23];
#pragma unroll
        for (int i = 0; i < 23; i++) {
            float s = 0.f;
#pragma unroll
            for (int w = 0; w < 8; w++) s += sred[i][w];
            r[i] = s;
        }
        float nt = fmaxf(sqrtf(r[0]), 1e-12f);
        float ntf = fmaxf(sqrtf(r[1]), 1e-12f);
        bool ctrl = tok < 7;
        float sc[7];
#pragma unroll
        for (int k = 0; k < 7; k++) {
            float na = fmaxf(sqrtf(r[16 + k]), 1e-12f);
            sc[k] = ctrl ? r[2 + k] / (nt * na) : r[9 + k] / (ntf * na);
        }
        float mx = -1e30f;
#pragma unroll
        for (int k = 0; k < 7; k++) mx = fmaxf(mx, 5.0f * sc[k]);
        float ex[7], se = 0.f;
#pragma unroll
        for (int k = 0; k < 7; k++) { ex[k] = expf(5.0f * sc[k] - mx); se += ex[k]; }
        int am = 0;
        float best = -1.0f, ent = 0.f;
#pragma unroll
        for (int k = 0; k < 7; k++) {
            float p = ex[k] / se;
            pi_out[b * 7 + k] = p;
            if (p > best) { best = p; am = k; }
            ent -= p * logf(p + 1e-8f);
        }
        g_ksel[b] = am;
        float gsum = c2b[0];
#pragma unroll
        for (int j = 0; j < 16; j++) {
            float hv = c1w[j * 2 + 0] * ent + c1b[j];
            hv = fmaxf(hv, 0.f);
            gsum += c2w[j] * hv;
        }
        g_gamma[b] = fmaxf(gsum, 0.f) + log1pf(expf(-fabsf(gsum)));
    }
}

// ---------------- grouping + tile map + barrier reset (deterministic) ----------
__global__ void group_kernel() {
    int i = threadIdx.x;
    if (i < GRID_DEQ) g_norms[i] = 0.f;
    if (i == 0) {
        int c[NK];
#pragma unroll
        for (int k = 0; k < NK; k++) c[k] = 0;
        for (int b = 0; b < NB; b++) {
            int k = g_ksel[b];
            g_rows[k * NB + (c[k]++)] = b;
        }
        int t = 0;
#pragma unroll
        for (int k = 0; k < NK; k++) {
            g_cnt[k] = c[k];
            for (int m0 = 0; m0 < c[k]; m0 += 32) {
                g_mt_k[t] = k; g_mt_m0[t] = m0; t++;
            }
        }
        g_mtcnt = t;
        g_cnt_bar = 0u;
        g_epoch_v = 0u;
        g_done_v = 0;
    }
}

// ---------------- generic GEMM BM=64 (decoder)  C = epi(A @ B^T + bias) -------
template <int EPI>
__global__ void __launch_bounds__(256) gemm_nt(const float* __restrict__ A, int lda,
                                               const float* __restrict__ Bm, int ldb,
                                               const float* __restrict__ bias,
                                               float* __restrict__ C, int ldc, int Kdim) {
    __shared__ unsigned long long As2[32][64];
    __shared__ float Bs[32][64];
    const int m0 = blockIdx.x * 64, n0 = blockIdx.y * 64;
    const int tid = threadIdx.x;
    const int tn = tid & 15, tm = tid >> 4;
    unsigned long long accv[4][2];
#pragma unroll
    for (int r = 0; r < 4; r++) { accv[r][0] = 0ull; accv[r][1] = 0ull; }
    const int lm = tid >> 3;
    const int lk = (tid & 7) << 2;
    for (int k0 = 0; k0 < Kdim; k0 += 32) {
#pragma unroll
        for (int q = 0; q < 2; q++) {
            int m = lm + q * 32;
            float4 v = *(const float4*)(A + (size_t)(m0 + m) * lda + (k0 + lk));
            As2[lk + 0][m] = pack2(v.x, v.x);
            As2[lk + 1][m] = pack2(v.y, v.y);
            As2[lk + 2][m] = pack2(v.z, v.z);
            As2[lk + 3][m] = pack2(v.w, v.w);
            float4 w = *(const float4*)(Bm + (size_t)(n0 + m) * ldb + (k0 + lk));
            Bs[lk + 0][m] = w.x; Bs[lk + 1][m] = w.y; Bs[lk + 2][m] = w.z; Bs[lk + 3][m] = w.w;
        }
        __syncthreads();
#pragma unroll
        for (int kk = 0; kk < 32; kk++) {
            ulonglong2 b = *(const ulonglong2*)&Bs[kk][tn * 4];
            ulonglong2 a01 = *(const ulonglong2*)&As2[kk][tm * 4];
            ulonglong2 a23 = *(const ulonglong2*)&As2[kk][tm * 4 + 2];
            accv[0][0] = fma2(a01.x, b.x, accv[0][0]); accv[0][1] = fma2(a01.x, b.y, accv[0][1]);
            accv[1][0] = fma2(a01.y, b.x, accv[1][0]); accv[1][1] = fma2(a01.y, b.y, accv[1][1]);
            accv[2][0] = fma2(a23.x, b.x, accv[2][0]); accv[2][1] = fma2(a23.x, b.y, accv[2][1]);
            accv[3][0] = fma2(a23.y, b.x, accv[3][0]); accv[3][1] = fma2(a23.y, b.y, accv[3][1]);
        }
        __syncthreads();
    }
    int n = n0 + tn * 4;
    float4 bv = *(const float4*)(bias + n);
#pragma unroll
    for (int r = 0; r < 4; r++) {
        int m = m0 + tm * 4 + r;
        float2 p0 = unpack2(accv[r][0]);
        float2 p1 = unpack2(accv[r][1]);
        float4 o;
        o.x = p0.x + bv.x; o.y = p0.y + bv.y; o.z = p1.x + bv.z; o.w = p1.y + bv.w;
        if (EPI == 1) { o.x = tanhf(o.x); o.y = tanhf(o.y); o.z = tanhf(o.z); o.w = tanhf(o.w); }
        if (EPI == 2) { o.x = sigmoidf_(o.x); o.y = sigmoidf_(o.y); o.z = sigmoidf_(o.z); o.w = sigmoidf_(o.w); }
        *(float4*)(C + (size_t)m * ldc + n) = o;
    }
}

// ---------------- GEMM BM=32 (stab layers; 2x the grid of BM=64) --------------
template <int EPI>
__global__ void __launch_bounds__(256) gemm_nt32(const float* __restrict__ A, int lda,
                                                 const float* __restrict__ Bm, int ldb,
                                                 const float* __restrict__ bias,
                                                 float* __restrict__ C, int ldc, int Kdim) {
    __shared__ unsigned long long As2[32][32];
    __shared__ float Bs[32][64];
    const int m0 = blockIdx.x * 32, n0 = blockIdx.y * 64;
    const int tid = threadIdx.x;
    const int tn = tid & 15, tm = tid >> 4;   // tm 0..15 -> 2 rows each
    unsigned long long acc[2][2];
    acc[0][0] = acc[0][1] = acc[1][0] = acc[1][1] = 0ull;
    const int lm = tid >> 3;                  // 0..31
    const int lk = (tid & 7) << 2;
    for (int k0 = 0; k0 < Kdim; k0 += 32) {
        {
            float4 v = *(const float4*)(A + (size_t)(m0 + lm) * lda + (k0 + lk));
            As2[lk + 0][lm] = pack2(v.x, v.x);
            As2[lk + 1][lm] = pack2(v.y, v.y);
            As2[lk + 2][lm] = pack2(v.z, v.z);
            As2[lk + 3][lm] = pack2(v.w, v.w);
        }
#pragma unroll
        for (int q = 0; q < 2; q++) {
            int m = lm + q * 32;
            float4 w = *(const float4*)(Bm + (size_t)(n0 + m) * ldb + (k0 + lk));
            Bs[lk + 0][m] = w.x; Bs[lk + 1][m] = w.y; Bs[lk + 2][m] = w.z; Bs[lk + 3][m] = w.w;
        }
        __syncthreads();
#pragma unroll
        for (int kk = 0; kk < 32; kk++) {
            ulonglong2 b = *(const ulonglong2*)&Bs[kk][tn * 4];
            ulonglong2 a = *(const ulonglong2*)&As2[kk][tm * 2];
            acc[0][0] = fma2(a.x, b.x, acc[0][0]); acc[0][1] = fma2(a.x, b.y, acc[0][1]);
            acc[1][0] = fma2(a.y, b.x, acc[1][0]); acc[1][1] = fma2(a.y, b.y, acc[1][1]);
        }
        __syncthreads();
    }
    int n = n0 + tn * 4;
    float4 bv = *(const float4*)(bias + n);
#pragma unroll
    for (int r = 0; r < 2; r++) {
        int m = m0 + tm * 2 + r;
        float2 p0 = unpack2(acc[r][0]);
        float2 p1 = unpack2(acc[r][1]);
        float4 o;
        o.x = p0.x + bv.x; o.y = p0.y + bv.y; o.z = p1.x + bv.z; o.w = p1.y + bv.w;
        if (EPI == 1) { o.x = tanhf(o.x); o.y = tanhf(o.y); o.z = tanhf(o.z); o.w = tanhf(o.w); }
        if (EPI == 2) { o.x = sigmoidf_(o.x); o.y = sigmoidf_(o.y); o.z = sigmoidf_(o.z); o.w = sigmoidf_(o.w); }
        *(float4*)(C + (size_t)m * ldc + n) = o;
    }
}

// ---------------- persistent DEQ: tile compute ---------------------------------
// MODE 0: acc = xcat @ [U;V][kg]  -> store c, z=tanh(c), nrm=||z||^2
// MODE 1: acc = zin  @ W[kg]      -> z=tanh(acc+c),      nrm=||z-zin||^2
template <int MODE>
__device__ __forceinline__ float deq_compute(
    int tid, int kg, int n0, int cnt, const int* rs,
    unsigned long long (*As2)[32], float (*Bs)[64],
    const float* __restrict__ G1, const float* __restrict__ G2,
    const float* __restrict__ zin, float* __restrict__ zout) {
    const int tn = tid & 15, tm = tid >> 4;
    unsigned long long acc[4][2];
#pragma unroll
    for (int r = 0; r < 4; r++) { acc[r][0] = 0ull; acc[r][1] = 0ull; }
    const int KD = (MODE == 0) ? 2 * ND : ND;
    for (int k0 = 0; k0 < KD; k0 += 32) {
#pragma unroll
        for (int q = 0; q < 2; q++) {
            int id = tid + q * 128;
            int m = id >> 3, kq = (id & 7) << 2;
            int rr = rs[m];
            float4 v;
            if (MODE == 0) v = *(const float4*)(g_xcat + (size_t)rr * 2 * ND + k0 + kq);
            else           v = __ldcg((const float4*)(zin + (size_t)rr * ND + k0 + kq));
            As2[kq + 0][m] = pack2(v.x, v.x);
            As2[kq + 1][m] = pack2(v.y, v.y);
            As2[kq + 2][m] = pack2(v.z, v.z);
            As2[kq + 3][m] = pack2(v.w, v.w);
        }
#pragma unroll
        for (int q = 0; q < 4; q++) {
            int id = tid + q * 128;
            int kk = id >> 4, eq = (id & 15) << 2;
            int kglob = k0 + kk;
            const float* bp;
            if (MODE == 0)
                bp = (kglob < ND)
                         ? (G1 + (size_t)kg * ND * ND + (size_t)kglob * ND + n0 + eq)
                         : (G2 + (size_t)kg * ND * ND + (size_t)(kglob - ND) * ND + n0 + eq);
            else
                bp = G1 + (size_t)kg * ND * ND + (size_t)kglob * ND + n0 + eq;
            *(float4*)&Bs[kk][eq] = *(const float4*)bp;
        }
        __syncthreads();
#pragma unroll
        for (int kk = 0; kk < 32; kk++) {
            ulonglong2 b = *(const ulonglong2*)&Bs[kk][tn * 4];
            ulonglong2 a01 = *(const ulonglong2*)&As2[kk][tm * 4];
            ulonglong2 a23 = *(const ulonglong2*)&As2[kk][tm * 4 + 2];
            acc[0][0] = fma2(a01.x, b.x, acc[0][0]); acc[0][1] = fma2(a01.x, b.y, acc[0][1]);
            acc[1][0] = fma2(a01.y, b.x, acc[1][0]); acc[1][1] = fma2(a01.y, b.y, acc[1][1]);
            acc[2][0] = fma2(a23.x, b.x, acc[2][0]); acc[2][1] = fma2(a23.x, b.y, acc[2][1]);
            acc[3][0] = fma2(a23.y, b.x, acc[3][0]); acc[3][1] = fma2(a23.y, b.y, acc[3][1]);
        }
        __syncthreads();
    }
    int n = n0 + tn * 4;
    float nrm = 0.f;
#pragma unroll
    for (int r = 0; r < 4; r++) {
        int mi = tm * 4 + r;
        if (mi < cnt) {
            int row = rs[mi];
            float2 p0 = unpack2(acc[r][0]);
            float2 p1 = unpack2(acc[r][1]);
            float4 zv;
            if (MODE == 0) {
                float4 cv = make_float4(p0.x, p0.y, p1.x, p1.y);
                *(float4*)(g_c + (size_t)row * ND + n) = cv;
                zv = make_float4(tanhf(cv.x), tanhf(cv.y), tanhf(cv.z), tanhf(cv.w));
                nrm += zv.x * zv.x + zv.y * zv.y + zv.z * zv.z + zv.w * zv.w;
            } else {
                float4 cv = *(const float4*)(g_c + (size_t)row * ND + n);  // immutable after phase0
                zv = make_float4(tanhf(p0.x + cv.x), tanhf(p0.y + cv.y),
                                 tanhf(p1.x + cv.z), tanhf(p1.y + cv.w));
                float4 old = __ldcg((const float4*)(zin + (size_t)row * ND + n));
                float dx = zv.x - old.x, dy = zv.y - old.y, dz = zv.z - old.z, dw = zv.w - old.w;
                nrm += dx * dx + dy * dy + dz * dz + dw * dw;
            }
            *(float4*)(zout + (size_t)row * ND + n) = zv;
        }
    }
    return nrm;
}

// grid barrier with embedded deterministic norm reduction + done flag
__device__ __forceinline__ bool deq_barrier(int tid, unsigned ep, int* s_done_p) {
    __syncthreads();
    if (tid == 0) {
        __threadfence();
        unsigned a = atomicAdd(&g_cnt_bar, 1u);
        if (a == (unsigned)(GRID_DEQ - 1)) {
            float s = 0.f;
#pragma unroll
            for (int i = 0; i < GRID_DEQ / 4; i++) {
                float4 v = __ldcg((const float4*)(g_norms + i * 4));
                s += (v.x + v.y) + (v.z + v.w);
            }
            if (s < 1e-8f) g_done_v = 1;   // ||dz|| < 1e-4
            g_cnt_bar = 0u;
            __threadfence();
            *(volatile unsigned*)&g_epoch_v = ep;
        } else {
            while (*(volatile unsigned*)&g_epoch_v < ep) __nanosleep(64);
            __threadfence();
        }
        *s_done_p = *(volatile int*)&g_done_v;
    }
    __syncthreads();
    return *s_done_p != 0;
}

__global__ void __launch_bounds__(128, 2) deq_kernel(
    const float* __restrict__ W, const float* __restrict__ U, const float* __restrict__ V,
    const float* __restrict__ h, float* __restrict__ out_h) {
    __shared__ unsigned long long As2[32][32];
    __shared__ float Bs[32][64];
    __shared__ int rs[32];
    __shared__ float swr[4];
    __shared__ int s_done;

    const int tid = threadIdx.x;
    const int bid = blockIdx.x;
    const int T = g_mtcnt * 16;
    const bool active = bid < T;
    int kg = 0, n0 = 0, cnt = 0;
    if (active) {
        int mt = bid >> 4;
        n0 = (bid & 15) << 6;
        kg = g_mt_k[mt];
        int m0 = g_mt_m0[mt];
        cnt = g_cnt[kg] - m0; if (cnt > 32) cnt = 32;
        if (tid < 32) rs[tid] = g_rows[kg * NB + m0 + (tid < cnt ? tid : 0)];
    }
    __syncthreads();

    int lane = tid & 31, wid = tid >> 5;
    unsigned ep = 0;
    bool done = false;

    // eval #1: c = xcat @ [U;V], z1 = tanh(c)
    if (active) {
        float nrm = deq_compute<0>(tid, kg, n0, cnt, rs, As2, Bs, U, V, nullptr, g_zA);
#pragma unroll
        for (int o = 16; o > 0; o >>= 1) nrm += __shfl_down_sync(0xffffffffu, nrm, o);
        if (lane == 0) swr[wid] = nrm;
        __syncthreads();
        if (tid == 0) g_norms[bid] = (swr[0] + swr[1]) + (swr[2] + swr[3]);
    }
    done = deq_barrier(tid, ++ep, &s_done);

    const float* zin = g_zA;
    float* zout = g_zB;
    for (int it = 2; it <= 40 && !done; it++) {
        if (active) {
            float nrm = deq_compute<1>(tid, kg, n0, cnt, rs, As2, Bs, W, nullptr, zin, zout);
#pragma unroll
            for (int o = 16; o > 0; o >>= 1) nrm += __shfl_down_sync(0xffffffffu, nrm, o);
            if (lane == 0) swr[wid] = nrm;
            __syncthreads();
            if (tid == 0) g_norms[bid] = (swr[0] + swr[1]) + (swr[2] + swr[3]);
        }
        done = deq_barrier(tid, ++ep, &s_done);
        const float* t = zout; zout = (float*)zin; zin = t;
    }

    // combine: h_next = h + gamma * alpha_local * z_star   (this block's tile)
    if (active) {
        const int tn = tid & 15, tm = tid >> 4;
        int n = n0 + tn * 4;
#pragma unroll
        for (int r = 0; r < 4; r++) {
            int mi = tm * 4 + r;
            if (mi < cnt) {
                int row = rs[mi];
                float4 z = __ldcg((const float4*)(zin + (size_t)row * ND + n));
                float ga = g_gamma[row];
                float4 al = *(const float4*)(g_alocal + (size_t)row * ND + n);
                float4 hv = *(const float4*)(h + (size_t)row * ND + n);
                float4 o;
                o.x = fmaf(ga * al.x, z.x, hv.x);
                o.y = fmaf(ga * al.y, z.y, hv.y);
                o.z = fmaf(ga * al.z, z.z, hv.z);
                o.w = fmaf(ga * al.w, z.w, hv.w);
                *(float4*)(out_h + (size_t)row * ND + n) = o;
            }
        }
    }
}

// ---------------- launch ----------------
extern "C" void kernel_launch(void* const* d_in, const int* in_sizes, int n_in,
                              void* d_out, int out_size) {
    (void)in_sizes; (void)n_in; (void)out_size;
    const float* h        = (const float*)d_in[0];
    const float* fiber_s  = (const float*)d_in[1];
    const float* fiber_e  = (const float*)d_in[2];
    const int*   token_idx= (const int*)d_in[3];
    const float* op_emb   = (const float*)d_in[4];
    const float* num_w    = (const float*)d_in[5];
    const float* num_b    = (const float*)d_in[6];
    const float* addr     = (const float*)d_in[7];
    const float* W        = (const float*)d_in[8];
    const float* U        = (const float*)d_in[9];
    const float* V        = (const float*)d_in[10];
    const float* fs_w     = (const float*)d_in[11];
    const float* fs_b     = (const float*)d_in[12];
    const float* fe_w     = (const float*)d_in[13];
    const float* fe_b     = (const float*)d_in[14];
    const float* s1w      = (const float*)d_in[15];
    const float* s1b      = (const float*)d_in[16];
    const float* s2w      = (const float*)d_in[17];
    const float* s2b      = (const float*)d_in[18];
    const float* c1w      = (const float*)d_in[19];
    const float* c1b      = (const float*)d_in[20];
    const float* c2w      = (const float*)d_in[21];
    const float* c2b      = (const float*)d_in[22];
    const float* dec_w    = (const float*)d_in[23];
    const float* dec_b    = (const float*)d_in[24];

    float *xcat, *stabh, *alocal;
    cudaGetSymbolAddress((void**)&xcat, g_xcat);
    cudaGetSymbolAddress((void**)&stabh, g_stabh);
    cudaGetSymbolAddress((void**)&alocal, g_alocal);

    float* out        = (float*)d_out;
    float* out_h      = out;                                         // [256,1024]
    float* out_logits = out + (size_t)NB * ND;                       // [256,32000]
    float* out_pi     = out + (size_t)NB * ND + (size_t)NB * NVOC;   // [256,7]

    prep_kernel<<<NB, 256>>>(h, fiber_s, fiber_e, token_idx, op_emb, num_w, num_b, addr,
                             fs_w, fs_b, fe_w, fe_b, c1w, c1b, c2w, c2b, out_pi);
    group_kernel<<<1, 256>>>();

    // stab network (needed by deq epilogue)
    gemm_nt32<1><<<dim3(8, 16), 256>>>(xcat, 2048, s1w, 2048, s1b, stabh, 1024, 2048);
    gemm_nt32<2><<<dim3(8, 16), 256>>>(stabh, 1024, s2w, 1024, s2b, alocal, 1024, 1024);

    // persistent DEQ: all fixed-point iterations + early exit + combine
    deq_kernel<<<GRID_DEQ, 128>>>(W, U, V, h, out_h);

    // decoder: logits = h_next @ dec_w^T + dec_b
    gemm_nt<0><<<dim3(4, 500), 256>>>(out_h, 1024, dec_w, 1024, dec_b, out_logits, 32000, 1024);
}

// round 17
// speedup vs baseline: 2.2020x; 1.0421x over previous
#include <cuda_runtime.h>
#include <math.h>

#define NB 256
#define ND 1024
#define NK 7
#define NVOC 32000
#define MAXT 14                 // max sum_k ceil(cnt_k/32)
#define GRID_DEQ (MAXT * 16)    // 224 blocks, one 32x64 tile each

// ---------------- scratch (static device globals; no allocation) ----------------
__device__ float g_xcat[NB * 2 * ND];   // [h | f_emb] per row (2048 wide)
__device__ float g_c[NB * ND];          // h@U[k] + f@V[k]
__device__ float g_zA[NB * ND];
__device__ float g_zB[NB * ND];
__device__ float g_stabh[NB * ND];
__device__ float g_alocal[NB * ND];
__device__ float g_gamma[NB];
__device__ int   g_ksel[NB];
__device__ int   g_rows[NK * NB];
__device__ int   g_cnt[NK];
__device__ int   g_mt_k[MAXT];
__device__ int   g_mt_m0[MAXT];
__device__ int   g_mtcnt;
__device__ float g_nacc[2];             // parity norm accumulators
__device__ unsigned g_cnt_bar;
__device__ unsigned g_epoch_v;
__device__ int   g_done_v;

// ---------------- f32x2 helpers ----------------
__device__ __forceinline__ unsigned long long fma2(unsigned long long a,
                                                   unsigned long long b,
                                                   unsigned long long c) {
    unsigned long long d;
    asm("fma.rn.f32x2 %0, %1, %2, %3;" : "=l"(d) : "l"(a), "l"(b), "l"(c));
    return d;
}
__device__ __forceinline__ unsigned long long pack2(float x, float y) {
    unsigned int lo = __float_as_uint(x), hi = __float_as_uint(y);
    return ((unsigned long long)hi << 32) | (unsigned long long)lo;
}
__device__ __forceinline__ float2 unpack2(unsigned long long v) {
    return make_float2(__uint_as_float((unsigned int)(v & 0xffffffffull)),
                       __uint_as_float((unsigned int)(v >> 32)));
}
__device__ __forceinline__ float sigmoidf_(float x) { return 1.0f / (1.0f + expf(-x)); }

// ---------------- prep: embeddings, routing, gamma, pi ----------------
__global__ void prep_kernel(const float* __restrict__ h, const float* __restrict__ fiber_s,
                            const float* __restrict__ fiber_e, const int* __restrict__ token_idx,
                            const float* __restrict__ op_emb, const float* __restrict__ num_w,
                            const float* __restrict__ num_b, const float* __restrict__ addr,
                            const float* __restrict__ fs_w, const float* __restrict__ fs_b,
                            const float* __restrict__ fe_w, const float* __restrict__ fe_b,
                            const float* __restrict__ c1w, const float* __restrict__ c1b,
                            const float* __restrict__ c2w, const float* __restrict__ c2b,
                            float* __restrict__ pi_out) {
    int b = blockIdx.x;
    int tid = threadIdx.x;
    int tok = token_idx[b];
    bool isnum = tok >= 7;
    float numval = (float)tok - 7.0f;
    int opk = min(max(tok, 0), 6);
    float fsv = fiber_s[b], fev = fiber_e[b];

    float acc[23];
#pragma unroll
    for (int i = 0; i < 23; i++) acc[i] = 0.f;

#pragma unroll
    for (int j = 0; j < 4; j++) {
        int d = tid + j * 256;
        float te = isnum ? (numval * num_w[d] + num_b[d]) : op_emb[opk * ND + d];
        float fv = tanhf(fsv * fs_w[d] + fs_b[d] + fev * fe_w[d] + fe_b[d]);
        g_xcat[(size_t)b * 2 * ND + d] = h[(size_t)b * ND + d];
        g_xcat[(size_t)b * 2 * ND + ND + d] = fv;
        float tf = te + fv;
        acc[0] += te * te;
        acc[1] += tf * tf;
#pragma unroll
        for (int k = 0; k < 7; k++) {
            float a = addr[k * ND + d];
            acc[2 + k] += te * a;
            acc[9 + k] += tf * a;
            acc[16 + k] += a * a;
        }
    }
    __shared__ float sred[23][8];
    int lane = tid & 31, wid = tid >> 5;
#pragma unroll
    for (int i = 0; i < 23; i++) {
        float v = acc[i];
#pragma unroll
        for (int o = 16; o > 0; o >>= 1) v += __shfl_down_sync(0xffffffffu, v, o);
        if (lane == 0) sred[i][wid] = v;
    }
    __syncthreads();
    if (tid == 0) {
        float r[23];
#pragma unroll
        for (int i = 0; i < 23; i++) {
            float s = 0.f;
#pragma unroll
            for (int w = 0; w < 8; w++) s += sred[i][w];
            r[i] = s;
        }
        float nt = fmaxf(sqrtf(r[0]), 1e-12f);
        float ntf = fmaxf(sqrtf(r[1]), 1e-12f);
        bool ctrl = tok < 7;
        float sc[7];
#pragma unroll
        for (int k = 0; k < 7; k++) {
            float na = fmaxf(sqrtf(r[16 + k]), 1e-12f);
            sc[k] = ctrl ? r[2 + k] / (nt * na) : r[9 + k] / (ntf * na);
        }
        float mx = -1e30f;
#pragma unroll
        for (int k = 0; k < 7; k++) mx = fmaxf(mx, 5.0f * sc[k]);
        float ex[7], se = 0.f;
#pragma unroll
        for (int k = 0; k < 7; k++) { ex[k] = expf(5.0f * sc[k] - mx); se += ex[k]; }
        int am = 0;
        float best = -1.0f, ent = 0.f;
#pragma unroll
        for (int k = 0; k < 7; k++) {
            float p = ex[k] / se;
            pi_out[b * 7 + k] = p;
            if (p > best) { best = p; am = k; }
            ent -= p * logf(p + 1e-8f);
        }
        g_ksel[b] = am;
        float gsum = c2b[0];
#pragma unroll
        for (int j = 0; j < 16; j++) {
            float hv = c1w[j * 2 + 0] * ent + c1b[j];
            hv = fmaxf(hv, 0.f);
            gsum += c2w[j] * hv;
        }
        g_gamma[b] = fmaxf(gsum, 0.f) + log1pf(expf(-fabsf(gsum)));
    }
}

// ---------------- grouping + tile map + barrier reset (deterministic) ----------
__global__ void group_kernel() {
    if (threadIdx.x == 0) {
        int c[NK];
#pragma unroll
        for (int k = 0; k < NK; k++) c[k] = 0;
        for (int b = 0; b < NB; b++) {
            int k = g_ksel[b];
            g_rows[k * NB + (c[k]++)] = b;
        }
        int t = 0;
#pragma unroll
        for (int k = 0; k < NK; k++) {
            g_cnt[k] = c[k];
            for (int m0 = 0; m0 < c[k]; m0 += 32) {
                g_mt_k[t] = k; g_mt_m0[t] = m0; t++;
            }
        }
        g_mtcnt = t;
        g_cnt_bar = 0u;
        g_epoch_v = 0u;
        g_done_v = 0;
        g_nacc[0] = 0.f;
        g_nacc[1] = 0.f;
    }
}

// ---------------- decoder GEMM BM=64/BN=64/256thr  C = A @ B^T + bias ---------
template <int EPI>
__global__ void __launch_bounds__(256) gemm_nt(const float* __restrict__ A, int lda,
                                               const float* __restrict__ Bm, int ldb,
                                               const float* __restrict__ bias,
                                               float* __restrict__ C, int ldc, int Kdim) {
    __shared__ unsigned long long As2[32][64];
    __shared__ float Bs[32][64];
    const int m0 = blockIdx.x * 64, n0 = blockIdx.y * 64;
    const int tid = threadIdx.x;
    const int tn = tid & 15, tm = tid >> 4;
    unsigned long long accv[4][2];
#pragma unroll
    for (int r = 0; r < 4; r++) { accv[r][0] = 0ull; accv[r][1] = 0ull; }
    const int lm = tid >> 3;
    const int lk = (tid & 7) << 2;
    for (int k0 = 0; k0 < Kdim; k0 += 32) {
#pragma unroll
        for (int q = 0; q < 2; q++) {
            int m = lm + q * 32;
            float4 v = *(const float4*)(A + (size_t)(m0 + m) * lda + (k0 + lk));
            As2[lk + 0][m] = pack2(v.x, v.x);
            As2[lk + 1][m] = pack2(v.y, v.y);
            As2[lk + 2][m] = pack2(v.z, v.z);
            As2[lk + 3][m] = pack2(v.w, v.w);
            float4 w = *(const float4*)(Bm + (size_t)(n0 + m) * ldb + (k0 + lk));
            Bs[lk + 0][m] = w.x; Bs[lk + 1][m] = w.y; Bs[lk + 2][m] = w.z; Bs[lk + 3][m] = w.w;
        }
        __syncthreads();
#pragma unroll
        for (int kk = 0; kk < 32; kk++) {
            ulonglong2 b = *(const ulonglong2*)&Bs[kk][tn * 4];
            ulonglong2 a01 = *(const ulonglong2*)&As2[kk][tm * 4];
            ulonglong2 a23 = *(const ulonglong2*)&As2[kk][tm * 4 + 2];
            accv[0][0] = fma2(a01.x, b.x, accv[0][0]); accv[0][1] = fma2(a01.x, b.y, accv[0][1]);
            accv[1][0] = fma2(a01.y, b.x, accv[1][0]); accv[1][1] = fma2(a01.y, b.y, accv[1][1]);
            accv[2][0] = fma2(a23.x, b.x, accv[2][0]); accv[2][1] = fma2(a23.x, b.y, accv[2][1]);
            accv[3][0] = fma2(a23.y, b.x, accv[3][0]); accv[3][1] = fma2(a23.y, b.y, accv[3][1]);
        }
        __syncthreads();
    }
    int n = n0 + tn * 4;
    float4 bv = *(const float4*)(bias + n);
#pragma unroll
    for (int r = 0; r < 4; r++) {
        int m = m0 + tm * 4 + r;
        float2 p0 = unpack2(accv[r][0]);
        float2 p1 = unpack2(accv[r][1]);
        float4 o;
        o.x = p0.x + bv.x; o.y = p0.y + bv.y; o.z = p1.x + bv.z; o.w = p1.y + bv.w;
        if (EPI == 1) { o.x = tanhf(o.x); o.y = tanhf(o.y); o.z = tanhf(o.z); o.w = tanhf(o.w); }
        if (EPI == 2) { o.x = sigmoidf_(o.x); o.y = sigmoidf_(o.y); o.z = sigmoidf_(o.z); o.w = sigmoidf_(o.w); }
        *(float4*)(C + (size_t)m * ldc + n) = o;
    }
}

// ---------------- stab GEMM BM=32/BN=64/128thr, double-buffered ----------------
template <int EPI>
__global__ void __launch_bounds__(128) gemm_nt128(const float* __restrict__ A, int lda,
                                                  const float* __restrict__ Bm, int ldb,
                                                  const float* __restrict__ bias,
                                                  float* __restrict__ C, int ldc, int Kdim) {
    __shared__ unsigned long long As2[2][32][32];
    __shared__ float Bs[2][32][64];
    const int m0 = blockIdx.x * 32, n0 = blockIdx.y * 64;
    const int tid = threadIdx.x;
    const int tn = tid & 15, tm = tid >> 4;   // tm 0..7 -> 4 rows each
    const int lm = tid >> 3;                  // 0..15
    const int lk = (tid & 7) << 2;
    unsigned long long acc[4][2];
#pragma unroll
    for (int r = 0; r < 4; r++) { acc[r][0] = 0ull; acc[r][1] = 0ull; }

    float4 ra[2], rb[4];
    auto LD = [&](int c) {
        int k0 = c << 5;
#pragma unroll
        for (int q = 0; q < 2; q++)
            ra[q] = *(const float4*)(A + (size_t)(m0 + lm + q * 16) * lda + k0 + lk);
#pragma unroll
        for (int q = 0; q < 4; q++)
            rb[q] = *(const float4*)(Bm + (size_t)(n0 + lm + q * 16) * ldb + k0 + lk);
    };
    auto ST = [&](int bb) {
#pragma unroll
        for (int q = 0; q < 2; q++) {
            int m = lm + q * 16;
            As2[bb][lk + 0][m] = pack2(ra[q].x, ra[q].x);
            As2[bb][lk + 1][m] = pack2(ra[q].y, ra[q].y);
            As2[bb][lk + 2][m] = pack2(ra[q].z, ra[q].z);
            As2[bb][lk + 3][m] = pack2(ra[q].w, ra[q].w);
        }
#pragma unroll
        for (int q = 0; q < 4; q++) {
            int m = lm + q * 16;
            Bs[bb][lk + 0][m] = rb[q].x; Bs[bb][lk + 1][m] = rb[q].y;
            Bs[bb][lk + 2][m] = rb[q].z; Bs[bb][lk + 3][m] = rb[q].w;
        }
    };

    const int NC = Kdim >> 5;
    LD(0); ST(0); __syncthreads();
    for (int c = 0; c < NC; c++) {
        if (c + 1 < NC) LD(c + 1);
        int bb = c & 1;
#pragma unroll
        for (int kk = 0; kk < 32; kk++) {
            ulonglong2 b = *(const ulonglong2*)&Bs[bb][kk][tn * 4];
            ulonglong2 a01 = *(const ulonglong2*)&As2[bb][kk][tm * 4];
            ulonglong2 a23 = *(const ulonglong2*)&As2[bb][kk][tm * 4 + 2];
            acc[0][0] = fma2(a01.x, b.x, acc[0][0]); acc[0][1] = fma2(a01.x, b.y, acc[0][1]);
            acc[1][0] = fma2(a01.y, b.x, acc[1][0]); acc[1][1] = fma2(a01.y, b.y, acc[1][1]);
            acc[2][0] = fma2(a23.x, b.x, acc[2][0]); acc[2][1] = fma2(a23.x, b.y, acc[2][1]);
            acc[3][0] = fma2(a23.y, b.x, acc[3][0]); acc[3][1] = fma2(a23.y, b.y, acc[3][1]);
        }
        __syncthreads();
        if (c + 1 < NC) { ST((c + 1) & 1); __syncthreads(); }
    }
    int n = n0 + tn * 4;
    float4 bv = *(const float4*)(bias + n);
#pragma unroll
    for (int r = 0; r < 4; r++) {
        int m = m0 + tm * 4 + r;
        float2 p0 = unpack2(acc[r][0]);
        float2 p1 = unpack2(acc[r][1]);
        float4 o;
        o.x = p0.x + bv.x; o.y = p0.y + bv.y; o.z = p1.x + bv.z; o.w = p1.y + bv.w;
        if (EPI == 1) { o.x = tanhf(o.x); o.y = tanhf(o.y); o.z = tanhf(o.z); o.w = tanhf(o.w); }
        if (EPI == 2) { o.x = sigmoidf_(o.x); o.y = sigmoidf_(o.y); o.z = sigmoidf_(o.z); o.w = sigmoidf_(o.w); }
        *(float4*)(C + (size_t)m * ldc + n) = o;
    }
}

// ---------------- persistent DEQ: double-buffered tile compute -----------------
// MODE 0: acc = xcat @ [U;V][kg]  -> store c, z=tanh(c)
// MODE 1: acc = zin  @ W[kg]      -> z=tanh(acc+c), nrm=||z-zin||^2
template <int MODE>
__device__ __forceinline__ float deq_compute(
    int tid, int kg, int n0, int cnt, const int* rs,
    unsigned long long (*As2)[32][32], float (*Bs)[32][64],
    const float* __restrict__ G1, const float* __restrict__ G2,
    const float* __restrict__ zin, float* __restrict__ zout) {
    const int tn = tid & 15, tm = tid >> 4;
    unsigned long long acc[4][2];
#pragma unroll
    for (int r = 0; r < 4; r++) { acc[r][0] = 0ull; acc[r][1] = 0ull; }

    const int kq = (tid & 7) << 2;
    int am[2], bk[4], be[4];
#pragma unroll
    for (int q = 0; q < 2; q++) { int id = tid + q * 128; am[q] = id >> 3; }
#pragma unroll
    for (int q = 0; q < 4; q++) { int id = tid + q * 128; bk[q] = id >> 4; be[q] = (id & 15) << 2; }

    float4 ra[2], rb[4];
    auto LD = [&](int c) {
        int k0 = c << 5;
#pragma unroll
        for (int q = 0; q < 2; q++) {
            int rr = rs[am[q]];
            if (MODE == 0) ra[q] = *(const float4*)(g_xcat + (size_t)rr * 2048 + k0 + kq);
            else           ra[q] = __ldcg((const float4*)(zin + (size_t)rr * ND + k0 + kq));
        }
#pragma unroll
        for (int q = 0; q < 4; q++) {
            int kglob = k0 + bk[q];
            const float* bp;
            if (MODE == 0)
                bp = (kglob < ND)
                         ? (G1 + (size_t)kg * ND * ND + (size_t)kglob * ND + n0 + be[q])
                         : (G2 + (size_t)kg * ND * ND + (size_t)(kglob - ND) * ND + n0 + be[q]);
            else
                bp = G1 + (size_t)kg * ND * ND + (size_t)kglob * ND + n0 + be[q];
            rb[q] = *(const float4*)bp;
        }
    };
    auto ST = [&](int bb) {
#pragma unroll
        for (int q = 0; q < 2; q++) {
            int m = am[q];
            As2[bb][kq + 0][m] = pack2(ra[q].x, ra[q].x);
            As2[bb][kq + 1][m] = pack2(ra[q].y, ra[q].y);
            As2[bb][kq + 2][m] = pack2(ra[q].z, ra[q].z);
            As2[bb][kq + 3][m] = pack2(ra[q].w, ra[q].w);
        }
#pragma unroll
        for (int q = 0; q < 4; q++) *(float4*)&Bs[bb][bk[q]][be[q]] = rb[q];
    };

    const int NC = (MODE == 0) ? 64 : 32;
    LD(0); ST(0); __syncthreads();
    for (int c = 0; c < NC; c++) {
        if (c + 1 < NC) LD(c + 1);
        int bb = c & 1;
#pragma unroll
        for (int kk = 0; kk < 32; kk++) {
            ulonglong2 b = *(const ulonglong2*)&Bs[bb][kk][tn * 4];
            ulonglong2 a01 = *(const ulonglong2*)&As2[bb][kk][tm * 4];
            ulonglong2 a23 = *(const ulonglong2*)&As2[bb][kk][tm * 4 + 2];
            acc[0][0] = fma2(a01.x, b.x, acc[0][0]); acc[0][1] = fma2(a01.x, b.y, acc[0][1]);
            acc[1][0] = fma2(a01.y, b.x, acc[1][0]); acc[1][1] = fma2(a01.y, b.y, acc[1][1]);
            acc[2][0] = fma2(a23.x, b.x, acc[2][0]); acc[2][1] = fma2(a23.x, b.y, acc[2][1]);
            acc[3][0] = fma2(a23.y, b.x, acc[3][0]); acc[3][1] = fma2(a23.y, b.y, acc[3][1]);
        }
        __syncthreads();
        if (c + 1 < NC) { ST((c + 1) & 1); __syncthreads(); }
    }

    int n = n0 + tn * 4;
    float nrm = 0.f;
#pragma unroll
    for (int r = 0; r < 4; r++) {
        int mi = tm * 4 + r;
        if (mi < cnt) {
            int row = rs[mi];
            float2 p0 = unpack2(acc[r][0]);
            float2 p1 = unpack2(acc[r][1]);
            float4 zv;
            if (MODE == 0) {
                float4 cv = make_float4(p0.x, p0.y, p1.x, p1.y);
                *(float4*)(g_c + (size_t)row * ND + n) = cv;
                zv = make_float4(tanhf(cv.x), tanhf(cv.y), tanhf(cv.z), tanhf(cv.w));
            } else {
                float4 cv = *(const float4*)(g_c + (size_t)row * ND + n);
                zv = make_float4(tanhf(p0.x + cv.x), tanhf(p0.y + cv.y),
                                 tanhf(p1.x + cv.z), tanhf(p1.y + cv.w));
                float4 old = __ldcg((const float4*)(zin + (size_t)row * ND + n));
                float dx = zv.x - old.x, dy = zv.y - old.y, dz = zv.z - old.z, dw = zv.w - old.w;
                nrm += dx * dx + dy * dy + dz * dz + dw * dw;
            }
            __stcg((float4*)(zout + (size_t)row * ND + n), zv);
        }
    }
    return nrm;
}

// grid barrier: norm folded into arrival via one float atomicAdd per block.
// chk=false on epochs with no accumulated norms (the MODE-0 epoch) — the R16 bug
// was checking the never-written parity slot there and exiting at iteration 1.
__device__ __forceinline__ bool deq_barrier(int tid, unsigned ep, float blknorm,
                                            bool addnorm, bool chk, int* s_done_p) {
    __syncthreads();
    if (tid == 0) {
        __threadfence();
        if (addnorm) {
            atomicAdd(&g_nacc[ep & 1], blknorm);
            __threadfence();
        }
        unsigned a = atomicAdd(&g_cnt_bar, 1u);
        if (a == (unsigned)(GRID_DEQ - 1)) {
            g_cnt_bar = 0u;
            if (chk) {
                float s = *(volatile float*)&g_nacc[ep & 1];
                if (s < 1e-8f) *(volatile int*)&g_done_v = 1;  // ||dz|| < 1e-4
            }
            *(volatile float*)&g_nacc[(ep & 1) ^ 1] = 0.f;     // reset for epoch ep+1
            __threadfence();
            *(volatile unsigned*)&g_epoch_v = ep;
        } else {
            while (*(volatile unsigned*)&g_epoch_v < ep) __nanosleep(32);
        }
        __threadfence();
        *s_done_p = *(volatile int*)&g_done_v;
    }
    __syncthreads();
    return *s_done_p != 0;
}

__global__ void __launch_bounds__(128, 2) deq_kernel(
    const float* __restrict__ W, const float* __restrict__ U, const float* __restrict__ V,
    const float* __restrict__ h, float* __restrict__ out_h) {
    __shared__ unsigned long long As2[2][32][32];
    __shared__ float Bs[2][32][64];
    __shared__ int rs[32];
    __shared__ float swr[4];
    __shared__ int s_done;

    const int tid = threadIdx.x;
    const int bid = blockIdx.x;
    const int T = g_mtcnt * 16;
    const bool active = bid < T;
    int kg = 0, n0 = 0, cnt = 0;
    if (active) {
        int mt = bid >> 4;
        n0 = (bid & 15) << 6;
        kg = g_mt_k[mt];
        int m0 = g_mt_m0[mt];
        cnt = g_cnt[kg] - m0; if (cnt > 32) cnt = 32;
        if (tid < 32) rs[tid] = g_rows[kg * NB + m0 + (tid < cnt ? tid : 0)];
    }
    __syncthreads();

    int lane = tid & 31, wid = tid >> 5;
    unsigned ep = 0;
    bool done = false;

    // eval #1: c = xcat @ [U;V], z1 = tanh(c). Reference's iter-1 exit test is
    // ||z1|| < 1e-4 which cannot trigger here (||z1|| ~ 1e2) — skip the check.
    if (active) (void)deq_compute<0>(tid, kg, n0, cnt, rs, As2, Bs, U, V, nullptr, g_zA);
    done = deq_barrier(tid, ++ep, 0.f, false, false, &s_done);

    const float* zin = g_zA;
    float* zout = g_zB;
    for (int it = 2; it <= 40 && !done; it++) {
        float blknorm = 0.f;
        if (active) {
            float nrm = deq_compute<1>(tid, kg, n0, cnt, rs, As2, Bs, W, nullptr, zin, zout);
#pragma unroll
            for (int o = 16; o > 0; o >>= 1) nrm += __shfl_down_sync(0xffffffffu, nrm, o);
            if (lane == 0) swr[wid] = nrm;
            __syncthreads();
            if (tid == 0) blknorm = (swr[0] + swr[1]) + (swr[2] + swr[3]);
        }
        done = deq_barrier(tid, ++ep, blknorm, active, true, &s_done);
        const float* t = zout; zout = (float*)zin; zin = t;
    }

    // combine: h_next = h + gamma * alpha_local * z_star   (this block's tile)
    if (active) {
        const int tn = tid & 15, tm = tid >> 4;
        int n = n0 + tn * 4;
#pragma unroll
        for (int r = 0; r < 4; r++) {
            int mi = tm * 4 + r;
            if (mi < cnt) {
                int row = rs[mi];
                float4 z = __ldcg((const float4*)(zin + (size_t)row * ND + n));
                float ga = g_gamma[row];
                float4 al = *(const float4*)(g_alocal + (size_t)row * ND + n);
                float4 hv = *(const float4*)(h + (size_t)row * ND + n);
                float4 o;
                o.x = fmaf(ga * al.x, z.x, hv.x);
                o.y = fmaf(ga * al.y, z.y, hv.y);
                o.z = fmaf(ga * al.z, z.z, hv.z);
                o.w = fmaf(ga * al.w, z.w, hv.w);
                *(float4*)(out_h + (size_t)row * ND + n) = o;
            }
        }
    }
}

// ---------------- launch ----------------
extern "C" void kernel_launch(void* const* d_in, const int* in_sizes, int n_in,
                              void* d_out, int out_size) {
    (void)in_sizes; (void)n_in; (void)out_size;
    const float* h        = (const float*)d_in[0];
    const float* fiber_s  = (const float*)d_in[1];
    const float* fiber_e  = (const float*)d_in[2];
    const int*   token_idx= (const int*)d_in[3];
    const float* op_emb   = (const float*)d_in[4];
    const float* num_w    = (const float*)d_in[5];
    const float* num_b    = (const float*)d_in[6];
    const float* addr     = (const float*)d_in[7];
    const float* W        = (const float*)d_in[8];
    const float* U        = (const float*)d_in[9];
    const float* V        = (const float*)d_in[10];
    const float* fs_w     = (const float*)d_in[11];
    const float* fs_b     = (const float*)d_in[12];
    const float* fe_w     = (const float*)d_in[13];
    const float* fe_b     = (const float*)d_in[14];
    const float* s1w      = (const float*)d_in[15];
    const float* s1b      = (const float*)d_in[16];
    const float* s2w      = (const float*)d_in[17];
    const float* s2b      = (const float*)d_in[18];
    const float* c1w      = (const float*)d_in[19];
    const float* c1b      = (const float*)d_in[20];
    const float* c2w      = (const float*)d_in[21];
    const float* c2b      = (const float*)d_in[22];
    const float* dec_w    = (const float*)d_in[23];
    const float* dec_b    = (const float*)d_in[24];

    float *xcat, *stabh, *alocal;
    cudaGetSymbolAddress((void**)&xcat, g_xcat);
    cudaGetSymbolAddress((void**)&stabh, g_stabh);
    cudaGetSymbolAddress((void**)&alocal, g_alocal);

    float* out        = (float*)d_out;
    float* out_h      = out;                                         // [256,1024]
    float* out_logits = out + (size_t)NB * ND;                       // [256,32000]
    float* out_pi     = out + (size_t)NB * ND + (size_t)NB * NVOC;   // [256,7]

    prep_kernel<<<NB, 256>>>(h, fiber_s, fiber_e, token_idx, op_emb, num_w, num_b, addr,
                             fs_w, fs_b, fe_w, fe_b, c1w, c1b, c2w, c2b, out_pi);
    group_kernel<<<1, 32>>>();

    // stab network (needed by deq epilogue) — balanced 128-thread tiles, 1 block/SM
    gemm_nt128<1><<<dim3(8, 16), 128>>>(xcat, 2048, s1w, 2048, s1b, stabh, 1024, 2048);
    gemm_nt128<2><<<dim3(8, 16), 128>>>(stabh, 1024, s2w, 1024, s2b, alocal, 1024, 1024);

    // persistent DEQ: all fixed-point iterations + early exit + combine
    deq_kernel<<<GRID_DEQ, 128>>>(W, U, V, h, out_h);

    // decoder: logits = h_next @ dec_w^T + dec_b
    gemm_nt<0><<<dim3(4, 500), 256>>>(out_h, 1024, dec_w, 1024, dec_b, out_logits, 32000, 1024);
}